// round 13
// baseline (speedup 1.0000x reference)
#include <cuda_runtime.h>
#include <cuda_fp16.h>
#include <math.h>
#include <cstdint>

#define DM   1024
#define NH   16
#define HD   64
#define DFF  4096
#define BB   2
#define LL   2048
#define MTOT (BB*LL)
#define HSZ  ((size_t)NH*BB*LL*HD)

// ---------------- scratch (static device globals; allocation-free) ----------
__device__ __half g_srch[(size_t)MTOT*DM];
__device__ __half g_Wqkvh[(size_t)DM*3*DM];
__device__ float  g_bqkv[3*DM];
__device__ __half g_Woh[(size_t)DM*DM];
__device__ __half g_W1h[(size_t)DM*DFF];
__device__ __half g_W2h[(size_t)DFF*DM];
__device__ __half g_QKVh[3*HSZ];
__device__ __half g_attnh[(size_t)MTOT*DM];
__device__ float  g_proj[(size_t)MTOT*DM];
__device__ float  g_x[(size_t)MTOT*DM];
__device__ __half g_xh[(size_t)MTOT*DM];
__device__ __half g_ff1h[(size_t)MTOT*DFF];
__device__ float  g_ff2[(size_t)MTOT*DM];

// ---------------- helpers ------------------------------------------------------
__device__ __forceinline__ void mma_f16(float* d, const uint32_t* a, const uint32_t* b) {
    asm volatile(
        "mma.sync.aligned.m16n8k16.row.col.f32.f16.f16.f32 "
        "{%0,%1,%2,%3}, {%4,%5,%6,%7}, {%8,%9}, {%0,%1,%2,%3};"
        : "+f"(d[0]), "+f"(d[1]), "+f"(d[2]), "+f"(d[3])
        : "r"(a[0]), "r"(a[1]), "r"(a[2]), "r"(a[3]), "r"(b[0]), "r"(b[1]));
}
__device__ __forceinline__ void ldm_x4(uint32_t& r0, uint32_t& r1, uint32_t& r2, uint32_t& r3,
                                       uint32_t addr) {
    asm volatile("ldmatrix.sync.aligned.m8n8.x4.shared.b16 {%0,%1,%2,%3}, [%4];"
                 : "=r"(r0), "=r"(r1), "=r"(r2), "=r"(r3) : "r"(addr));
}
__device__ __forceinline__ void ldm_x4t(uint32_t& r0, uint32_t& r1, uint32_t& r2, uint32_t& r3,
                                        uint32_t addr) {
    asm volatile("ldmatrix.sync.aligned.m8n8.x4.trans.shared.b16 {%0,%1,%2,%3}, [%4];"
                 : "=r"(r0), "=r"(r1), "=r"(r2), "=r"(r3) : "r"(addr));
}
__device__ __forceinline__ uint32_t h2u(float x, float y) {
    __half2 h = __float22half2_rn(make_float2(x, y));
    return *(uint32_t*)&h;
}
__device__ __forceinline__ void cp16(uint32_t dst, const void* src) {
    asm volatile("cp.async.cg.shared.global [%0], [%1], 16;" :: "r"(dst), "l"(src));
}
#define CP_COMMIT() asm volatile("cp.async.commit_group;" ::: "memory")
#define CP_WAIT(N)  asm volatile("cp.async.wait_group %0;" :: "n"(N) : "memory")

// ---------------- one-shot conversion / concat kernel -------------------------
#define SRC_E (4194304u)
#define WE    (1048576u)

__device__ __forceinline__ void cvt8(const float* in, __half* out) {
    float4 a = *(const float4*)in;
    float4 b = *(const float4*)(in + 4);
    uint4 o;
    o.x = h2u(a.x, a.y); o.y = h2u(a.z, a.w);
    o.z = h2u(b.x, b.y); o.w = h2u(b.z, b.w);
    *(uint4*)out = o;
}

__global__ __launch_bounds__(256)
void conv_all(const float* __restrict__ src,
              const float* __restrict__ Wq, const float* __restrict__ Wk,
              const float* __restrict__ Wv, const float* __restrict__ Wo,
              const float* __restrict__ W1, const float* __restrict__ W2,
              const float* __restrict__ bq, const float* __restrict__ bk,
              const float* __restrict__ bv,
              __half* __restrict__ srch, __half* __restrict__ Wqkv,
              __half* __restrict__ Woh, __half* __restrict__ W1h,
              __half* __restrict__ W2h, float* __restrict__ bqkv)
{
    const unsigned g = blockIdx.x * 256 + threadIdx.x;
    if (g < 384) {
        int t = g >> 7;
        int i = (g & 127) * 8;
        const float* bp = (t == 0) ? bq : (t == 1) ? bk : bv;
        float4 a = *(const float4*)(bp + i);
        float4 b = *(const float4*)(bp + i + 4);
        *(float4*)(bqkv + t * 1024 + i)     = a;
        *(float4*)(bqkv + t * 1024 + i + 4) = b;
    }
    size_t i = (size_t)g * 8;
    if (i < SRC_E) {
        cvt8(src + i, srch + i);
    } else if (i < SRC_E + 3 * (size_t)WE) {
        size_t j = i - SRC_E;
        int t = (int)(j >> 20);
        size_t jj = j & (WE - 1);
        const float* W = (t == 0) ? Wq : (t == 1) ? Wk : Wv;
        size_t k = jj >> 10, n = jj & 1023;
        cvt8(W + jj, Wqkv + k * 3072 + t * 1024 + n);
    } else if (i < SRC_E + 4 * (size_t)WE) {
        size_t j = i - (SRC_E + 3 * (size_t)WE);
        cvt8(Wo + j, Woh + j);
    } else if (i < SRC_E + 4 * (size_t)WE + SRC_E) {
        size_t j = i - (SRC_E + 4 * (size_t)WE);
        cvt8(W1 + j, W1h + j);
    } else {
        size_t j = i - (SRC_E + 4 * (size_t)WE + SRC_E);
        cvt8(W2 + j, W2h + j);
    }
}

// ---------------- warp-mma FP16 GEMM: 128 thr, 128x128 tile, 64x64 warp tile -
// KC=32, 4-stage, depth-3 lookahead (the R9-validated pipeline).
// EPI 0: fp32 plain  1: gelu fp16  2: split-head qkv-concat fp16 (N=3072)
#define KC 32
#define AS_STRIDE 40
#define BS_STRIDE 136
#define ASB (128 * AS_STRIDE * 2)      // 10240 B
#define BSB (KC * BS_STRIDE * 2)       // 8704 B
#define NSTAGE 4
#define GEMM_SMEM (NSTAGE * (ASB + BSB))   // 75776 B

template<int EPI>
__global__ __launch_bounds__(128)
void wm_gemm(const __half* __restrict__ A, const __half* __restrict__ B,
             const float* __restrict__ bias, void* __restrict__ Cv,
             int M, int N, int K)
{
    extern __shared__ __align__(16) char smem[];
    const uint32_t As_base = (uint32_t)__cvta_generic_to_shared(smem);
    const uint32_t Bs_base = As_base + NSTAGE * ASB;

    const int tid  = threadIdx.x;
    const int wid  = tid >> 5;
    const int lane = tid & 31;
    const int lg   = lane & 3;
    const int grp  = lane >> 2;
    const int n0 = blockIdx.x * 128;
    const int m0 = blockIdx.y * 128;
    const int wm = (wid & 1) * 64;     // 2 warps in m, 64 rows each
    const int wn = (wid >> 1) * 64;    // 2 warps in n, 64 cols each

    // staging (128 threads): A 128x32 halves (row tid, 4 cp16)
    //                        B 32x128 halves (row tid>>2, 4 cp16)
    const int brow = tid >> 2, bcol = (tid & 3) * 32;
    const __half* Ap = A + (size_t)(m0 + tid) * K;
    const __half* Bp = B + (size_t)brow * N + n0 + bcol;
    const uint32_t a_dst = As_base + tid * (AS_STRIDE * 2);
    const uint32_t b_dst = Bs_base + brow * (BS_STRIDE * 2) + bcol * 2;

    const uint32_t a_addr0 = As_base +
        ((wm + (lane & 15)) * AS_STRIDE + (lane >> 4) * 8) * 2;
    const uint32_t b_addr0 = Bs_base +
        ((lane & 15) * BS_STRIDE + wn + (lane >> 4) * 8) * 2;

    float d[4][8][4];
    #pragma unroll
    for (int i = 0; i < 4; i++)
        #pragma unroll
        for (int j = 0; j < 8; j++)
            #pragma unroll
            for (int q = 0; q < 4; q++) d[i][j][q] = 0.f;

    const int C_CHUNKS = K >> 5;

    // prefetch chunks 0,1,2
    #pragma unroll
    for (int pc = 0; pc < 3; pc++) {
        #pragma unroll
        for (int i = 0; i < 4; i++) {
            cp16(a_dst + pc * ASB + i * 16, Ap + (size_t)pc * KC + i * 8);
            cp16(b_dst + pc * BSB + i * 16, Bp + (size_t)pc * KC * N + i * 8);
        }
        CP_COMMIT();
    }

    for (int c = 0; c < C_CHUNKS; c++) {
        const int rb = c & 3;
        CP_WAIT(2);
        __syncthreads();
        if (c + 3 < C_CHUNKS) {
            const int wb = (c + 3) & 3;
            #pragma unroll
            for (int i = 0; i < 4; i++) {
                cp16(a_dst + wb * ASB + i * 16, Ap + (size_t)(c + 3) * KC + i * 8);
                cp16(b_dst + wb * BSB + i * 16, Bp + (size_t)(c + 3) * KC * N + i * 8);
            }
        }
        CP_COMMIT();

        #pragma unroll
        for (int ks = 0; ks < 2; ks++) {
            uint32_t a[4][4], b[8][2];
            #pragma unroll
            for (int i = 0; i < 4; i++)
                ldm_x4(a[i][0], a[i][1], a[i][2], a[i][3],
                       a_addr0 + rb * ASB + (i * 16 * AS_STRIDE + ks * 16) * 2);
            #pragma unroll
            for (int j2 = 0; j2 < 4; j2++) {
                uint32_t r0, r1, r2, r3;
                ldm_x4t(r0, r1, r2, r3,
                        b_addr0 + rb * BSB + (ks * 16 * BS_STRIDE + j2 * 16) * 2);
                b[j2 * 2][0] = r0; b[j2 * 2][1] = r1;
                b[j2 * 2 + 1][0] = r2; b[j2 * 2 + 1][1] = r3;
            }
            #pragma unroll
            for (int i = 0; i < 4; i++)
                #pragma unroll
                for (int j = 0; j < 8; j++)
                    mma_f16(d[i][j], a[i], b[j]);
        }
    }

    // ---- epilogue ----
    #pragma unroll
    for (int i = 0; i < 4; i++) {
        const int r0 = m0 + wm + i * 16 + grp;
        #pragma unroll
        for (int j = 0; j < 8; j++) {
            const int c = n0 + wn + j * 8 + lg * 2;
            float2 v0, v1;
            v0.x = d[i][j][0] + bias[c];
            v0.y = d[i][j][1] + bias[c + 1];
            v1.x = d[i][j][2] + bias[c];
            v1.y = d[i][j][3] + bias[c + 1];
            if (EPI == 0) {
                float* C = (float*)Cv;
                *(float2*)(C + (size_t)r0 * N + c) = v0;
                *(float2*)(C + (size_t)(r0 + 8) * N + c) = v1;
            } else if (EPI == 1) {
                v0.x *= normcdff(v0.x); v0.y *= normcdff(v0.y);
                v1.x *= normcdff(v1.x); v1.y *= normcdff(v1.y);
                __half* C = (__half*)Cv;
                *(uint32_t*)(C + (size_t)r0 * N + c) = h2u(v0.x, v0.y);
                *(uint32_t*)(C + (size_t)(r0 + 8) * N + c) = h2u(v1.x, v1.y);
            } else {
                const int t_ = c >> 10, n = c & 1023;
                const int h = n >> 6, hd = n & 63;
                const int b0_ = r0 >> 11, l0 = r0 & 2047;
                const int r1 = r0 + 8;
                const int b1_ = r1 >> 11, l1 = r1 & 2047;
                __half* C = (__half*)Cv + (size_t)t_ * HSZ;
                *(uint32_t*)(C + ((size_t)((b0_ << 4) + h) * LL + l0) * HD + hd) = h2u(v0.x, v0.y);
                *(uint32_t*)(C + ((size_t)((b1_ << 4) + h) * LL + l1) * HD + hd) = h2u(v1.x, v1.y);
            }
        }
    }
}

// ---------------- flash attention: 128-query blocks, 8 warps -----------------
#define FS 72
#define KVB (64 * FS * 2)

__global__ __launch_bounds__(256)
void flash_mma(const __half* __restrict__ Q, const __half* __restrict__ Kg,
               const __half* __restrict__ Vg, __half* __restrict__ O)
{
    __shared__ __align__(16) uint16_t Qs[128][FS];
    __shared__ __align__(16) uint16_t Ks[2][64][FS];
    __shared__ __align__(16) uint16_t Vs[2][64][FS];

    const int tid  = threadIdx.x;
    const int wid  = tid >> 5;
    const int lane = tid & 31;
    const int grp  = lane >> 2;
    const int lg   = lane & 3;
    const int bh   = blockIdx.y;
    const int q0   = blockIdx.x * 128;

    const uint32_t Qb_s = (uint32_t)__cvta_generic_to_shared(&Qs[0][0]);
    const uint32_t Kb_s = (uint32_t)__cvta_generic_to_shared(&Ks[0][0][0]);
    const uint32_t Vb_s = (uint32_t)__cvta_generic_to_shared(&Vs[0][0][0]);

    const int qrow = tid >> 1, qcol = (tid & 1) * 32;
    const uint32_t q_dst = Qb_s + qrow * (FS * 2) + qcol * 2;
    const __half* Qp = Q + ((size_t)bh * LL + q0 + qrow) * HD + qcol;
    const int krow = tid >> 2, kcol = (tid & 3) * 16;
    const uint32_t k_dst = Kb_s + krow * (FS * 2) + kcol * 2;
    const uint32_t v_dst = Vb_s + krow * (FS * 2) + kcol * 2;
    const __half* Kp = Kg + ((size_t)bh * LL + krow) * HD + kcol;
    const __half* Vp = Vg + ((size_t)bh * LL + krow) * HD + kcol;

    #pragma unroll
    for (int i = 0; i < 4; i++) cp16(q_dst + i * 16, Qp + i * 8);
    CP_COMMIT();
    #pragma unroll
    for (int pt = 0; pt < 2; pt++) {
        #pragma unroll
        for (int i = 0; i < 2; i++) {
            cp16(k_dst + pt * KVB + i * 16, Kp + (size_t)pt * 64 * HD + i * 8);
            cp16(v_dst + pt * KVB + i * 16, Vp + (size_t)pt * 64 * HD + i * 8);
        }
        CP_COMMIT();
    }

    CP_WAIT(2);
    __syncthreads();
    uint32_t qa[4][4];
    {
        const uint32_t qaddr = Qb_s + ((wid * 16 + (lane & 15)) * FS + (lane >> 4) * 8) * 2;
        #pragma unroll
        for (int ks = 0; ks < 4; ks++)
            ldm_x4(qa[ks][0], qa[ks][1], qa[ks][2], qa[ks][3], qaddr + ks * 16 * 2);
    }

    const uint32_t kaddr = Kb_s +
        (((lane >> 4) * 8 + (lane & 7)) * FS + ((lane >> 3) & 1) * 8) * 2;
    const uint32_t vaddr = Vb_s + ((lane & 15) * FS + (lane >> 4) * 8) * 2;

    float m0 = -1e30f, m1 = -1e30f, l0 = 0.f, l1 = 0.f;
    float oacc[8][4];
    #pragma unroll
    for (int j = 0; j < 8; j++)
        #pragma unroll
        for (int q = 0; q < 4; q++) oacc[j][q] = 0.f;

    const int NT = LL / 64;
    for (int kt = 0; kt < NT; kt++) {
        const int buf = kt & 1;
        CP_WAIT(1);
        __syncthreads();

        float sacc[8][4];
        #pragma unroll
        for (int na = 0; na < 8; na++)
            #pragma unroll
            for (int q = 0; q < 4; q++) sacc[na][q] = 0.f;

        #pragma unroll
        for (int ks = 0; ks < 4; ks++) {
            #pragma unroll
            for (int na2 = 0; na2 < 4; na2++) {
                uint32_t b0, b1, b2, b3;
                ldm_x4(b0, b1, b2, b3,
                       kaddr + buf * KVB + (na2 * 16 * FS + ks * 16) * 2);
                uint32_t bb0[2] = {b0, b1};
                uint32_t bb1[2] = {b2, b3};
                mma_f16(sacc[na2 * 2], qa[ks], bb0);
                mma_f16(sacc[na2 * 2 + 1], qa[ks], bb1);
            }
        }
        #pragma unroll
        for (int na = 0; na < 8; na++) {
            sacc[na][0] *= 0.125f; sacc[na][1] *= 0.125f;
            sacc[na][2] *= 0.125f; sacc[na][3] *= 0.125f;
        }

        float tm0 = -1e30f, tm1 = -1e30f;
        #pragma unroll
        for (int na = 0; na < 8; na++) {
            tm0 = fmaxf(tm0, fmaxf(sacc[na][0], sacc[na][1]));
            tm1 = fmaxf(tm1, fmaxf(sacc[na][2], sacc[na][3]));
        }
        tm0 = fmaxf(tm0, __shfl_xor_sync(0xffffffffu, tm0, 1));
        tm0 = fmaxf(tm0, __shfl_xor_sync(0xffffffffu, tm0, 2));
        tm1 = fmaxf(tm1, __shfl_xor_sync(0xffffffffu, tm1, 1));
        tm1 = fmaxf(tm1, __shfl_xor_sync(0xffffffffu, tm1, 2));
        const float nm0 = fmaxf(m0, tm0), nm1 = fmaxf(m1, tm1);
        const float f0 = __expf(m0 - nm0), f1 = __expf(m1 - nm1);
        m0 = nm0; m1 = nm1;

        float s0 = 0.f, s1 = 0.f;
        uint32_t pa[4][4];
        #pragma unroll
        for (int na = 0; na < 8; na++) {
            float p0 = __expf(sacc[na][0] - nm0);
            float p1 = __expf(sacc[na][1] - nm0);
            float p2 = __expf(sacc[na][2] - nm1);
            float p3 = __expf(sacc[na][3] - nm1);
            s0 += p0 + p1; s1 += p2 + p3;
            pa[na >> 1][(na & 1) * 2 + 0] = h2u(p0, p1);
            pa[na >> 1][(na & 1) * 2 + 1] = h2u(p2, p3);
        }
        s0 += __shfl_xor_sync(0xffffffffu, s0, 1);
        s0 += __shfl_xor_sync(0xffffffffu, s0, 2);
        s1 += __shfl_xor_sync(0xffffffffu, s1, 1);
        s1 += __shfl_xor_sync(0xffffffffu, s1, 2);
        l0 = l0 * f0 + s0;
        l1 = l1 * f1 + s1;
        #pragma unroll
        for (int j = 0; j < 8; j++) {
            oacc[j][0] *= f0; oacc[j][1] *= f0;
            oacc[j][2] *= f1; oacc[j][3] *= f1;
        }

        #pragma unroll
        for (int ks = 0; ks < 4; ks++) {
            #pragma unroll
            for (int j2 = 0; j2 < 4; j2++) {
                uint32_t r0, r1, r2, r3;
                ldm_x4t(r0, r1, r2, r3,
                        vaddr + buf * KVB + (ks * 16 * FS + j2 * 16) * 2);
                uint32_t bb0[2] = {r0, r1};
                uint32_t bb1[2] = {r2, r3};
                mma_f16(oacc[j2 * 2], pa[ks], bb0);
                mma_f16(oacc[j2 * 2 + 1], pa[ks], bb1);
            }
        }
        __syncthreads();
        if (kt + 2 < NT) {
            #pragma unroll
            for (int i = 0; i < 2; i++) {
                cp16(k_dst + buf * KVB + i * 16, Kp + (size_t)(kt + 2) * 64 * HD + i * 8);
                cp16(v_dst + buf * KVB + i * 16, Vp + (size_t)(kt + 2) * 64 * HD + i * 8);
            }
        }
        CP_COMMIT();
    }

    const float inv0 = 1.f / l0, inv1 = 1.f / l1;
    const int b = bh >> 4, h = bh & 15;
    const int r0 = q0 + wid * 16 + grp;
    __half* O0 = O + ((size_t)(b * LL + r0)) * DM + h * HD;
    __half* O1 = O0 + (size_t)8 * DM;
    #pragma unroll
    for (int j = 0; j < 8; j++) {
        *(uint32_t*)(O0 + j * 8 + 2 * lg) = h2u(oacc[j][0] * inv0, oacc[j][1] * inv0);
        *(uint32_t*)(O1 + j * 8 + 2 * lg) = h2u(oacc[j][2] * inv1, oacc[j][3] * inv1);
    }
}

// ---------------- warp-per-row residual add + LayerNorm (barrier-free) ------
template<bool WRITE_H>
__global__ __launch_bounds__(256)
void add_ln_k(const float* __restrict__ A, const float* __restrict__ B,
              const float* __restrict__ gamma, const float* __restrict__ beta,
              float* __restrict__ out, __half* __restrict__ outh)
{
    const int w = threadIdx.x >> 5, lane = threadIdx.x & 31;
    const int row = blockIdx.x * 8 + w;
    const float4* a = (const float4*)(A + (size_t)row * DM);
    const float4* b = (const float4*)(B + (size_t)row * DM);

    float4 v[8];
    float s = 0.f, q = 0.f;
    #pragma unroll
    for (int i = 0; i < 8; i++) {
        float4 va = a[lane + 32 * i];
        float4 vb = b[lane + 32 * i];
        va.x += vb.x; va.y += vb.y; va.z += vb.z; va.w += vb.w;
        v[i] = va;
        s += va.x + va.y + va.z + va.w;
        q += va.x * va.x + va.y * va.y + va.z * va.z + va.w * va.w;
    }
    #pragma unroll
    for (int o = 16; o > 0; o >>= 1) {
        s += __shfl_xor_sync(0xffffffffu, s, o);
        q += __shfl_xor_sync(0xffffffffu, q, o);
    }
    const float mean = s * (1.f / DM);
    const float var  = q * (1.f / DM) - mean * mean;
    const float rstd = rsqrtf(var + 1e-5f);

    #pragma unroll
    for (int i = 0; i < 8; i++) {
        const int c = (lane + 32 * i) * 4;
        float4 g  = *(const float4*)(gamma + c);
        float4 be = *(const float4*)(beta + c);
        float4 o;
        o.x = (v[i].x - mean) * rstd * g.x + be.x;
        o.y = (v[i].y - mean) * rstd * g.y + be.y;
        o.z = (v[i].z - mean) * rstd * g.z + be.z;
        o.w = (v[i].w - mean) * rstd * g.w + be.w;
        ((float4*)(out + (size_t)row * DM))[lane + 32 * i] = o;
        if (WRITE_H) {
            uint2 hh = make_uint2(h2u(o.x, o.y), h2u(o.z, o.w));
            *(uint2*)(outh + (size_t)row * DM + c) = hh;
        }
    }
}

// ---------------- launcher ---------------------------------------------------
extern "C" void kernel_launch(void* const* d_in, const int* in_sizes, int n_in,
                              void* d_out, int out_size)
{
    const float* src = (const float*)d_in[0];
    const float* Wq  = (const float*)d_in[1];  const float* bq = (const float*)d_in[2];
    const float* Wk  = (const float*)d_in[3];  const float* bk = (const float*)d_in[4];
    const float* Wv  = (const float*)d_in[5];  const float* bv = (const float*)d_in[6];
    const float* Wo  = (const float*)d_in[7];  const float* bo = (const float*)d_in[8];
    const float* W1  = (const float*)d_in[9];  const float* b1 = (const float*)d_in[10];
    const float* W2  = (const float*)d_in[11]; const float* b2 = (const float*)d_in[12];
    const float* gamma1 = (const float*)d_in[13]; const float* beta1 = (const float*)d_in[14];
    const float* gamma2 = (const float*)d_in[15]; const float* beta2 = (const float*)d_in[16];
    float* out = (float*)d_out;

    __half *srch, *Wqkvh, *Woh, *W1h, *W2h, *QKVh, *attnh, *xh, *ff1h;
    float  *bqkv, *proj, *x, *ff2;
    cudaGetSymbolAddress((void**)&srch,  g_srch);
    cudaGetSymbolAddress((void**)&Wqkvh, g_Wqkvh);
    cudaGetSymbolAddress((void**)&bqkv,  g_bqkv);
    cudaGetSymbolAddress((void**)&Woh,   g_Woh);
    cudaGetSymbolAddress((void**)&W1h,   g_W1h);
    cudaGetSymbolAddress((void**)&W2h,   g_W2h);
    cudaGetSymbolAddress((void**)&QKVh,  g_QKVh);
    cudaGetSymbolAddress((void**)&attnh, g_attnh);
    cudaGetSymbolAddress((void**)&xh,    g_xh);
    cudaGetSymbolAddress((void**)&ff1h,  g_ff1h);
    cudaGetSymbolAddress((void**)&proj,  g_proj);
    cudaGetSymbolAddress((void**)&x,     g_x);
    cudaGetSymbolAddress((void**)&ff2,   g_ff2);

    cudaFuncSetAttribute(wm_gemm<0>, cudaFuncAttributeMaxDynamicSharedMemorySize, GEMM_SMEM);
    cudaFuncSetAttribute(wm_gemm<1>, cudaFuncAttributeMaxDynamicSharedMemorySize, GEMM_SMEM);
    cudaFuncSetAttribute(wm_gemm<2>, cudaFuncAttributeMaxDynamicSharedMemorySize, GEMM_SMEM);

    conv_all<<<8192, 256>>>(src, Wq, Wk, Wv, Wo, W1, W2, bq, bk, bv,
                            srch, Wqkvh, Woh, W1h, W2h, bqkv);

    wm_gemm<2><<<dim3(3 * DM / 128, MTOT / 128), 128, GEMM_SMEM>>>(
        srch, Wqkvh, bqkv, QKVh, MTOT, 3 * DM, DM);

    flash_mma<<<dim3(LL / 128, BB * NH), 256>>>(QKVh, QKVh + HSZ, QKVh + 2 * HSZ, attnh);

    wm_gemm<0><<<dim3(DM / 128, MTOT / 128), 128, GEMM_SMEM>>>(attnh, Woh, bo, proj, MTOT, DM, DM);

    add_ln_k<true><<<MTOT / 8, 256>>>(src, proj, gamma1, beta1, x, xh);

    wm_gemm<1><<<dim3(DFF / 128, MTOT / 128), 128, GEMM_SMEM>>>(xh, W1h, b1, ff1h, MTOT, DFF, DM);
    wm_gemm<0><<<dim3(DM / 128, MTOT / 128), 128, GEMM_SMEM>>>(ff1h, W2h, b2, ff2, MTOT, DM, DFF);

    add_ln_k<false><<<MTOT / 8, 256>>>(x, ff2, gamma2, beta2, out, nullptr);
}

// round 16
// speedup vs baseline: 1.3686x; 1.3686x over previous
#include <cuda_runtime.h>
#include <cuda_fp16.h>
#include <math.h>
#include <cstdint>

#define DM   1024
#define NH   16
#define HD   64
#define DFF  4096
#define BB   2
#define LL   2048
#define MTOT (BB*LL)
#define HSZ  ((size_t)NH*BB*LL*HD)

// ---------------- scratch (static device globals; allocation-free) ----------
__device__ __half g_srch[(size_t)MTOT*DM];
__device__ __half g_Wqkvh[(size_t)DM*3*DM];
__device__ float  g_bqkv[3*DM];
__device__ __half g_Woh[(size_t)DM*DM];
__device__ __half g_W1h[(size_t)DM*DFF];
__device__ __half g_W2h[(size_t)DFF*DM];
__device__ __half g_QKVh[3*HSZ];
__device__ __half g_attnh[(size_t)MTOT*DM];
__device__ float  g_proj[(size_t)MTOT*DM];
__device__ float  g_x[(size_t)MTOT*DM];
__device__ __half g_xh[(size_t)MTOT*DM];
__device__ __half g_ff1h[(size_t)MTOT*DFF];
__device__ float  g_ff2[(size_t)MTOT*DM];

// ---------------- helpers ------------------------------------------------------
__device__ __forceinline__ void mma_f16(float* d, const uint32_t* a, const uint32_t* b) {
    asm volatile(
        "mma.sync.aligned.m16n8k16.row.col.f32.f16.f16.f32 "
        "{%0,%1,%2,%3}, {%4,%5,%6,%7}, {%8,%9}, {%0,%1,%2,%3};"
        : "+f"(d[0]), "+f"(d[1]), "+f"(d[2]), "+f"(d[3])
        : "r"(a[0]), "r"(a[1]), "r"(a[2]), "r"(a[3]), "r"(b[0]), "r"(b[1]));
}
__device__ __forceinline__ void ldm_x4(uint32_t& r0, uint32_t& r1, uint32_t& r2, uint32_t& r3,
                                       uint32_t addr) {
    asm volatile("ldmatrix.sync.aligned.m8n8.x4.shared.b16 {%0,%1,%2,%3}, [%4];"
                 : "=r"(r0), "=r"(r1), "=r"(r2), "=r"(r3) : "r"(addr));
}
__device__ __forceinline__ void ldm_x4t(uint32_t& r0, uint32_t& r1, uint32_t& r2, uint32_t& r3,
                                        uint32_t addr) {
    asm volatile("ldmatrix.sync.aligned.m8n8.x4.trans.shared.b16 {%0,%1,%2,%3}, [%4];"
                 : "=r"(r0), "=r"(r1), "=r"(r2), "=r"(r3) : "r"(addr));
}
__device__ __forceinline__ uint32_t h2u(float x, float y) {
    __half2 h = __float22half2_rn(make_float2(x, y));
    return *(uint32_t*)&h;
}
__device__ __forceinline__ void cp16(uint32_t dst, const void* src) {
    asm volatile("cp.async.cg.shared.global [%0], [%1], 16;" :: "r"(dst), "l"(src));
}
#define CP_COMMIT() asm volatile("cp.async.commit_group;" ::: "memory")
#define CP_WAIT(N)  asm volatile("cp.async.wait_group %0;" :: "n"(N) : "memory")

// ---------------- one-shot conversion / concat kernel -------------------------
#define SRC_E (4194304u)
#define WE    (1048576u)

__device__ __forceinline__ void cvt8(const float* in, __half* out) {
    float4 a = *(const float4*)in;
    float4 b = *(const float4*)(in + 4);
    uint4 o;
    o.x = h2u(a.x, a.y); o.y = h2u(a.z, a.w);
    o.z = h2u(b.x, b.y); o.w = h2u(b.z, b.w);
    *(uint4*)out = o;
}

__global__ __launch_bounds__(256)
void conv_all(const float* __restrict__ src,
              const float* __restrict__ Wq, const float* __restrict__ Wk,
              const float* __restrict__ Wv, const float* __restrict__ Wo,
              const float* __restrict__ W1, const float* __restrict__ W2,
              const float* __restrict__ bq, const float* __restrict__ bk,
              const float* __restrict__ bv,
              __half* __restrict__ srch, __half* __restrict__ Wqkv,
              __half* __restrict__ Woh, __half* __restrict__ W1h,
              __half* __restrict__ W2h, float* __restrict__ bqkv)
{
    const unsigned g = blockIdx.x * 256 + threadIdx.x;
    if (g < 384) {
        int t = g >> 7;
        int i = (g & 127) * 8;
        const float* bp = (t == 0) ? bq : (t == 1) ? bk : bv;
        float4 a = *(const float4*)(bp + i);
        float4 b = *(const float4*)(bp + i + 4);
        *(float4*)(bqkv + t * 1024 + i)     = a;
        *(float4*)(bqkv + t * 1024 + i + 4) = b;
    }
    size_t i = (size_t)g * 8;
    if (i < SRC_E) {
        cvt8(src + i, srch + i);
    } else if (i < SRC_E + 3 * (size_t)WE) {
        size_t j = i - SRC_E;
        int t = (int)(j >> 20);
        size_t jj = j & (WE - 1);
        const float* W = (t == 0) ? Wq : (t == 1) ? Wk : Wv;
        size_t k = jj >> 10, n = jj & 1023;
        cvt8(W + jj, Wqkv + k * 3072 + t * 1024 + n);
    } else if (i < SRC_E + 4 * (size_t)WE) {
        size_t j = i - (SRC_E + 3 * (size_t)WE);
        cvt8(Wo + j, Woh + j);
    } else if (i < SRC_E + 4 * (size_t)WE + SRC_E) {
        size_t j = i - (SRC_E + 4 * (size_t)WE);
        cvt8(W1 + j, W1h + j);
    } else {
        size_t j = i - (SRC_E + 4 * (size_t)WE + SRC_E);
        cvt8(W2 + j, W2h + j);
    }
}

// ---------------- warp-mma FP16 GEMM, KC=32, 4-stage, depth-3 (R9 optimum) ---
// EPI 0: fp32 plain  1: gelu fp16  2: split-head qkv-concat fp16 (N=3072,
//        Q-third pre-scaled by 1/sqrt(HD))
#define KC 32
#define AS_STRIDE 40
#define BS_STRIDE 136
#define ASB (128 * AS_STRIDE * 2)      // 10240 B
#define BSB (KC * BS_STRIDE * 2)       // 8704 B
#define NSTAGE 4
#define GEMM_SMEM (NSTAGE * (ASB + BSB))   // 75776 B

template<int EPI>
__global__ __launch_bounds__(256)
void wm_gemm(const __half* __restrict__ A, const __half* __restrict__ B,
             const float* __restrict__ bias, void* __restrict__ Cv,
             int M, int N, int K)
{
    extern __shared__ __align__(16) char smem[];
    const uint32_t As_base = (uint32_t)__cvta_generic_to_shared(smem);
    const uint32_t Bs_base = As_base + NSTAGE * ASB;

    const int tid  = threadIdx.x;
    const int wid  = tid >> 5;
    const int lane = tid & 31;
    const int lg   = lane & 3;
    const int grp  = lane >> 2;
    const int n0 = blockIdx.x * 128;
    const int m0 = blockIdx.y * 128;
    const int wm = (wid & 3) * 32;
    const int wn = (wid >> 2) * 64;

    // staging (KC=32): A 128x32 halves, B 32x128 halves; 2 cp16 each per thread
    const int arow = tid >> 1, acol = (tid & 1) * 16;
    const int brow = tid >> 3, bcol = (tid & 7) * 16;
    const __half* Ap = A + (size_t)(m0 + arow) * K + acol;
    const __half* Bp = B + (size_t)brow * N + n0 + bcol;
    const uint32_t a_dst = As_base + arow * (AS_STRIDE * 2) + acol * 2;
    const uint32_t b_dst = Bs_base + brow * (BS_STRIDE * 2) + bcol * 2;

    const uint32_t a_addr0 = As_base +
        ((wm + (lane & 15)) * AS_STRIDE + (lane >> 4) * 8) * 2;
    const uint32_t b_addr0 = Bs_base +
        ((lane & 15) * BS_STRIDE + wn + (lane >> 4) * 8) * 2;

    float d[2][8][4];
    #pragma unroll
    for (int i = 0; i < 2; i++)
        #pragma unroll
        for (int j = 0; j < 8; j++)
            #pragma unroll
            for (int q = 0; q < 4; q++) d[i][j][q] = 0.f;

    const int C_CHUNKS = K >> 5;

    // prefetch chunks 0,1,2
    #pragma unroll
    for (int pc = 0; pc < 3; pc++) {
        cp16(a_dst + pc * ASB,      Ap + pc * KC);
        cp16(a_dst + pc * ASB + 16, Ap + pc * KC + 8);
        cp16(b_dst + pc * BSB,      Bp + (size_t)pc * KC * N);
        cp16(b_dst + pc * BSB + 16, Bp + (size_t)pc * KC * N + 8);
        CP_COMMIT();
    }

    for (int c = 0; c < C_CHUNKS; c++) {
        const int rb = c & 3;
        CP_WAIT(2);
        __syncthreads();
        if (c + 3 < C_CHUNKS) {
            const int wb = (c + 3) & 3;
            cp16(a_dst + wb * ASB,      Ap + (size_t)(c + 3) * KC);
            cp16(a_dst + wb * ASB + 16, Ap + (size_t)(c + 3) * KC + 8);
            cp16(b_dst + wb * BSB,      Bp + (size_t)(c + 3) * KC * N);
            cp16(b_dst + wb * BSB + 16, Bp + (size_t)(c + 3) * KC * N + 8);
        }
        CP_COMMIT();

        #pragma unroll
        for (int ks = 0; ks < 2; ks++) {
            uint32_t a[2][4], b[8][2];
            #pragma unroll
            for (int i = 0; i < 2; i++)
                ldm_x4(a[i][0], a[i][1], a[i][2], a[i][3],
                       a_addr0 + rb * ASB + (i * 16 * AS_STRIDE + ks * 16) * 2);
            #pragma unroll
            for (int j2 = 0; j2 < 4; j2++) {
                uint32_t r0, r1, r2, r3;
                ldm_x4t(r0, r1, r2, r3,
                        b_addr0 + rb * BSB + (ks * 16 * BS_STRIDE + j2 * 16) * 2);
                b[j2 * 2][0] = r0; b[j2 * 2][1] = r1;
                b[j2 * 2 + 1][0] = r2; b[j2 * 2 + 1][1] = r3;
            }
            #pragma unroll
            for (int i = 0; i < 2; i++)
                #pragma unroll
                for (int j = 0; j < 8; j++)
                    mma_f16(d[i][j], a[i], b[j]);
        }
    }

    // ---- epilogue ----
    #pragma unroll
    for (int i = 0; i < 2; i++) {
        const int r0 = m0 + wm + i * 16 + grp;
        #pragma unroll
        for (int j = 0; j < 8; j++) {
            const int c = n0 + wn + j * 8 + lg * 2;
            float2 v0, v1;
            v0.x = d[i][j][0] + bias[c];
            v0.y = d[i][j][1] + bias[c + 1];
            v1.x = d[i][j][2] + bias[c];
            v1.y = d[i][j][3] + bias[c + 1];
            if (EPI == 0) {
                float* C = (float*)Cv;
                *(float2*)(C + (size_t)r0 * N + c) = v0;
                *(float2*)(C + (size_t)(r0 + 8) * N + c) = v1;
            } else if (EPI == 1) {
                v0.x *= normcdff(v0.x); v0.y *= normcdff(v0.y);
                v1.x *= normcdff(v1.x); v1.y *= normcdff(v1.y);
                __half* C = (__half*)Cv;
                *(uint32_t*)(C + (size_t)r0 * N + c) = h2u(v0.x, v0.y);
                *(uint32_t*)(C + (size_t)(r0 + 8) * N + c) = h2u(v1.x, v1.y);
            } else {
                const int t_ = c >> 10, n = c & 1023;
                if (t_ == 0) {     // Q third: fold 1/sqrt(HD) here
                    v0.x *= 0.125f; v0.y *= 0.125f;
                    v1.x *= 0.125f; v1.y *= 0.125f;
                }
                const int h = n >> 6, hd = n & 63;
                const int b0_ = r0 >> 11, l0 = r0 & 2047;
                const int r1 = r0 + 8;
                const int b1_ = r1 >> 11, l1 = r1 & 2047;
                __half* C = (__half*)Cv + (size_t)t_ * HSZ;
                *(uint32_t*)(C + ((size_t)((b0_ << 4) + h) * LL + l0) * HD + hd) = h2u(v0.x, v0.y);
                *(uint32_t*)(C + ((size_t)((b1_ << 4) + h) * LL + l1) * HD + hd) = h2u(v1.x, v1.y);
            }
        }
    }
}

// ---------------- flash attention: 128-query blocks, 8 warps -----------------
// Q arrives pre-scaled by 1/sqrt(HD) from the QKV epilogue.
#define FS 72
#define KVB (64 * FS * 2)

__global__ __launch_bounds__(256)
void flash_mma(const __half* __restrict__ Q, const __half* __restrict__ Kg,
               const __half* __restrict__ Vg, __half* __restrict__ O)
{
    __shared__ __align__(16) uint16_t Qs[128][FS];
    __shared__ __align__(16) uint16_t Ks[2][64][FS];
    __shared__ __align__(16) uint16_t Vs[2][64][FS];

    const int tid  = threadIdx.x;
    const int wid  = tid >> 5;
    const int lane = tid & 31;
    const int grp  = lane >> 2;
    const int lg   = lane & 3;
    const int bh   = blockIdx.y;
    const int q0   = blockIdx.x * 128;

    const uint32_t Qb_s = (uint32_t)__cvta_generic_to_shared(&Qs[0][0]);
    const uint32_t Kb_s = (uint32_t)__cvta_generic_to_shared(&Ks[0][0][0]);
    const uint32_t Vb_s = (uint32_t)__cvta_generic_to_shared(&Vs[0][0][0]);

    const int qrow = tid >> 1, qcol = (tid & 1) * 32;
    const uint32_t q_dst = Qb_s + qrow * (FS * 2) + qcol * 2;
    const __half* Qp = Q + ((size_t)bh * LL + q0 + qrow) * HD + qcol;
    const int krow = tid >> 2, kcol = (tid & 3) * 16;
    const uint32_t k_dst = Kb_s + krow * (FS * 2) + kcol * 2;
    const uint32_t v_dst = Vb_s + krow * (FS * 2) + kcol * 2;
    const __half* Kp = Kg + ((size_t)bh * LL + krow) * HD + kcol;
    const __half* Vp = Vg + ((size_t)bh * LL + krow) * HD + kcol;

    #pragma unroll
    for (int i = 0; i < 4; i++) cp16(q_dst + i * 16, Qp + i * 8);
    CP_COMMIT();
    #pragma unroll
    for (int pt = 0; pt < 2; pt++) {
        #pragma unroll
        for (int i = 0; i < 2; i++) {
            cp16(k_dst + pt * KVB + i * 16, Kp + (size_t)pt * 64 * HD + i * 8);
            cp16(v_dst + pt * KVB + i * 16, Vp + (size_t)pt * 64 * HD + i * 8);
        }
        CP_COMMIT();
    }

    CP_WAIT(2);
    __syncthreads();
    uint32_t qa[4][4];
    {
        const uint32_t qaddr = Qb_s + ((wid * 16 + (lane & 15)) * FS + (lane >> 4) * 8) * 2;
        #pragma unroll
        for (int ks = 0; ks < 4; ks++)
            ldm_x4(qa[ks][0], qa[ks][1], qa[ks][2], qa[ks][3], qaddr + ks * 16 * 2);
    }

    const uint32_t kaddr = Kb_s +
        (((lane >> 4) * 8 + (lane & 7)) * FS + ((lane >> 3) & 1) * 8) * 2;
    const uint32_t vaddr = Vb_s + ((lane & 15) * FS + (lane >> 4) * 8) * 2;

    float m0 = -1e30f, m1 = -1e30f, l0 = 0.f, l1 = 0.f;
    float oacc[8][4];
    #pragma unroll
    for (int j = 0; j < 8; j++)
        #pragma unroll
        for (int q = 0; q < 4; q++) oacc[j][q] = 0.f;

    const int NT = LL / 64;
    for (int kt = 0; kt < NT; kt++) {
        const int buf = kt & 1;
        CP_WAIT(1);
        __syncthreads();

        float sacc[8][4];
        #pragma unroll
        for (int na = 0; na < 8; na++)
            #pragma unroll
            for (int q = 0; q < 4; q++) sacc[na][q] = 0.f;

        #pragma unroll
        for (int ks = 0; ks < 4; ks++) {
            #pragma unroll
            for (int na2 = 0; na2 < 4; na2++) {
                uint32_t b0, b1, b2, b3;
                ldm_x4(b0, b1, b2, b3,
                       kaddr + buf * KVB + (na2 * 16 * FS + ks * 16) * 2);
                uint32_t bb0[2] = {b0, b1};
                uint32_t bb1[2] = {b2, b3};
                mma_f16(sacc[na2 * 2], qa[ks], bb0);
                mma_f16(sacc[na2 * 2 + 1], qa[ks], bb1);
            }
        }

        float tm0 = -1e30f, tm1 = -1e30f;
        #pragma unroll
        for (int na = 0; na < 8; na++) {
            tm0 = fmaxf(tm0, fmaxf(sacc[na][0], sacc[na][1]));
            tm1 = fmaxf(tm1, fmaxf(sacc[na][2], sacc[na][3]));
        }
        tm0 = fmaxf(tm0, __shfl_xor_sync(0xffffffffu, tm0, 1));
        tm0 = fmaxf(tm0, __shfl_xor_sync(0xffffffffu, tm0, 2));
        tm1 = fmaxf(tm1, __shfl_xor_sync(0xffffffffu, tm1, 1));
        tm1 = fmaxf(tm1, __shfl_xor_sync(0xffffffffu, tm1, 2));
        const float nm0 = fmaxf(m0, tm0), nm1 = fmaxf(m1, tm1);
        const float f0 = __expf(m0 - nm0), f1 = __expf(m1 - nm1);
        m0 = nm0; m1 = nm1;

        float s0 = 0.f, s1 = 0.f;
        uint32_t pa[4][4];
        #pragma unroll
        for (int na = 0; na < 8; na++) {
            float p0 = __expf(sacc[na][0] - nm0);
            float p1 = __expf(sacc[na][1] - nm0);
            float p2 = __expf(sacc[na][2] - nm1);
            float p3 = __expf(sacc[na][3] - nm1);
            s0 += p0 + p1; s1 += p2 + p3;
            pa[na >> 1][(na & 1) * 2 + 0] = h2u(p0, p1);
            pa[na >> 1][(na & 1) * 2 + 1] = h2u(p2, p3);
        }
        s0 += __shfl_xor_sync(0xffffffffu, s0, 1);
        s0 += __shfl_xor_sync(0xffffffffu, s0, 2);
        s1 += __shfl_xor_sync(0xffffffffu, s1, 1);
        s1 += __shfl_xor_sync(0xffffffffu, s1, 2);
        l0 = l0 * f0 + s0;
        l1 = l1 * f1 + s1;
        #pragma unroll
        for (int j = 0; j < 8; j++) {
            oacc[j][0] *= f0; oacc[j][1] *= f0;
            oacc[j][2] *= f1; oacc[j][3] *= f1;
        }

        #pragma unroll
        for (int ks = 0; ks < 4; ks++) {
            #pragma unroll
            for (int j2 = 0; j2 < 4; j2++) {
                uint32_t r0, r1, r2, r3;
                ldm_x4t(r0, r1, r2, r3,
                        vaddr + buf * KVB + (ks * 16 * FS + j2 * 16) * 2);
                uint32_t bb0[2] = {r0, r1};
                uint32_t bb1[2] = {r2, r3};
                mma_f16(oacc[j2 * 2], pa[ks], bb0);
                mma_f16(oacc[j2 * 2 + 1], pa[ks], bb1);
            }
        }
        __syncthreads();
        if (kt + 2 < NT) {
            #pragma unroll
            for (int i = 0; i < 2; i++) {
                cp16(k_dst + buf * KVB + i * 16, Kp + (size_t)(kt + 2) * 64 * HD + i * 8);
                cp16(v_dst + buf * KVB + i * 16, Vp + (size_t)(kt + 2) * 64 * HD + i * 8);
            }
        }
        CP_COMMIT();
    }

    const float inv0 = 1.f / l0, inv1 = 1.f / l1;
    const int b = bh >> 4, h = bh & 15;
    const int r0 = q0 + wid * 16 + grp;
    __half* O0 = O + ((size_t)(b * LL + r0)) * DM + h * HD;
    __half* O1 = O0 + (size_t)8 * DM;
    #pragma unroll
    for (int j = 0; j < 8; j++) {
        *(uint32_t*)(O0 + j * 8 + 2 * lg) = h2u(oacc[j][0] * inv0, oacc[j][1] * inv0);
        *(uint32_t*)(O1 + j * 8 + 2 * lg) = h2u(oacc[j][2] * inv1, oacc[j][3] * inv1);
    }
}

// ---------------- warp-per-row residual add + LayerNorm (barrier-free) ------
template<bool WRITE_H>
__global__ __launch_bounds__(256)
void add_ln_k(const float* __restrict__ A, const float* __restrict__ B,
              const float* __restrict__ gamma, const float* __restrict__ beta,
              float* __restrict__ out, __half* __restrict__ outh)
{
    const int w = threadIdx.x >> 5, lane = threadIdx.x & 31;
    const int row = blockIdx.x * 8 + w;
    const float4* a = (const float4*)(A + (size_t)row * DM);
    const float4* b = (const float4*)(B + (size_t)row * DM);

    float4 v[8];
    float s = 0.f, q = 0.f;
    #pragma unroll
    for (int i = 0; i < 8; i++) {
        float4 va = a[lane + 32 * i];
        float4 vb = b[lane + 32 * i];
        va.x += vb.x; va.y += vb.y; va.z += vb.z; va.w += vb.w;
        v[i] = va;
        s += va.x + va.y + va.z + va.w;
        q += va.x * va.x + va.y * va.y + va.z * va.z + va.w * va.w;
    }
    #pragma unroll
    for (int o = 16; o > 0; o >>= 1) {
        s += __shfl_xor_sync(0xffffffffu, s, o);
        q += __shfl_xor_sync(0xffffffffu, q, o);
    }
    const float mean = s * (1.f / DM);
    const float var  = q * (1.f / DM) - mean * mean;
    const float rstd = rsqrtf(var + 1e-5f);

    #pragma unroll
    for (int i = 0; i < 8; i++) {
        const int c = (lane + 32 * i) * 4;
        float4 g  = *(const float4*)(gamma + c);
        float4 be = *(const float4*)(beta + c);
        float4 o;
        o.x = (v[i].x - mean) * rstd * g.x + be.x;
        o.y = (v[i].y - mean) * rstd * g.y + be.y;
        o.z = (v[i].z - mean) * rstd * g.z + be.z;
        o.w = (v[i].w - mean) * rstd * g.w + be.w;
        ((float4*)(out + (size_t)row * DM))[lane + 32 * i] = o;
        if (WRITE_H) {
            uint2 hh = make_uint2(h2u(o.x, o.y), h2u(o.z, o.w));
            *(uint2*)(outh + (size_t)row * DM + c) = hh;
        }
    }
}

// ---------------- launcher ---------------------------------------------------
extern "C" void kernel_launch(void* const* d_in, const int* in_sizes, int n_in,
                              void* d_out, int out_size)
{
    const float* src = (const float*)d_in[0];
    const float* Wq  = (const float*)d_in[1];  const float* bq = (const float*)d_in[2];
    const float* Wk  = (const float*)d_in[3];  const float* bk = (const float*)d_in[4];
    const float* Wv  = (const float*)d_in[5];  const float* bv = (const float*)d_in[6];
    const float* Wo  = (const float*)d_in[7];  const float* bo = (const float*)d_in[8];
    const float* W1  = (const float*)d_in[9];  const float* b1 = (const float*)d_in[10];
    const float* W2  = (const float*)d_in[11]; const float* b2 = (const float*)d_in[12];
    const float* gamma1 = (const float*)d_in[13]; const float* beta1 = (const float*)d_in[14];
    const float* gamma2 = (const float*)d_in[15]; const float* beta2 = (const float*)d_in[16];
    float* out = (float*)d_out;

    __half *srch, *Wqkvh, *Woh, *W1h, *W2h, *QKVh, *attnh, *xh, *ff1h;
    float  *bqkv, *proj, *x, *ff2;
    cudaGetSymbolAddress((void**)&srch,  g_srch);
    cudaGetSymbolAddress((void**)&Wqkvh, g_Wqkvh);
    cudaGetSymbolAddress((void**)&bqkv,  g_bqkv);
    cudaGetSymbolAddress((void**)&Woh,   g_Woh);
    cudaGetSymbolAddress((void**)&W1h,   g_W1h);
    cudaGetSymbolAddress((void**)&W2h,   g_W2h);
    cudaGetSymbolAddress((void**)&QKVh,  g_QKVh);
    cudaGetSymbolAddress((void**)&attnh, g_attnh);
    cudaGetSymbolAddress((void**)&xh,    g_xh);
    cudaGetSymbolAddress((void**)&ff1h,  g_ff1h);
    cudaGetSymbolAddress((void**)&proj,  g_proj);
    cudaGetSymbolAddress((void**)&x,     g_x);
    cudaGetSymbolAddress((void**)&ff2,   g_ff2);

    cudaFuncSetAttribute(wm_gemm<0>, cudaFuncAttributeMaxDynamicSharedMemorySize, GEMM_SMEM);
    cudaFuncSetAttribute(wm_gemm<1>, cudaFuncAttributeMaxDynamicSharedMemorySize, GEMM_SMEM);
    cudaFuncSetAttribute(wm_gemm<2>, cudaFuncAttributeMaxDynamicSharedMemorySize, GEMM_SMEM);

    conv_all<<<8192, 256>>>(src, Wq, Wk, Wv, Wo, W1, W2, bq, bk, bv,
                            srch, Wqkvh, Woh, W1h, W2h, bqkv);

    wm_gemm<2><<<dim3(3 * DM / 128, MTOT / 128), 256, GEMM_SMEM>>>(
        srch, Wqkvh, bqkv, QKVh, MTOT, 3 * DM, DM);

    flash_mma<<<dim3(LL / 128, BB * NH), 256>>>(QKVh, QKVh + HSZ, QKVh + 2 * HSZ, attnh);

    wm_gemm<0><<<dim3(DM / 128, MTOT / 128), 256, GEMM_SMEM>>>(attnh, Woh, bo, proj, MTOT, DM, DM);

    add_ln_k<true><<<MTOT / 8, 256>>>(src, proj, gamma1, beta1, x, xh);

    wm_gemm<1><<<dim3(DFF / 128, MTOT / 128), 256, GEMM_SMEM>>>(xh, W1h, b1, ff1h, MTOT, DFF, DM);
    wm_gemm<0><<<dim3(DM / 128, MTOT / 128), 256, GEMM_SMEM>>>(ff1h, W2h, b2, ff2, MTOT, DM, DFF);

    add_ln_k<false><<<MTOT / 8, 256>>>(x, ff2, gamma2, beta2, out, nullptr);
}

// round 17
// speedup vs baseline: 1.4174x; 1.0356x over previous
#include <cuda_runtime.h>
#include <cuda_fp16.h>
#include <math.h>
#include <cstdint>

#define DM   1024
#define NH   16
#define HD   64
#define DFF  4096
#define BB   2
#define LL   2048
#define MTOT (BB*LL)
#define HSZ  ((size_t)NH*BB*LL*HD)

// ---------------- scratch (static device globals; allocation-free) ----------
__device__ __half g_srch[(size_t)MTOT*DM];
__device__ __half g_Wqkvh[(size_t)DM*3*DM];
__device__ float  g_bqkv[3*DM];
__device__ __half g_Woh[(size_t)DM*DM];
__device__ __half g_W1h[(size_t)DM*DFF];
__device__ __half g_W2h[(size_t)DFF*DM];
__device__ __half g_QKVh[3*HSZ];
__device__ __half g_attnh[(size_t)MTOT*DM];
__device__ float  g_proj[(size_t)MTOT*DM];
__device__ float  g_x[(size_t)MTOT*DM];
__device__ __half g_xh[(size_t)MTOT*DM];
__device__ __half g_ff1h[(size_t)MTOT*DFF];
__device__ float  g_ff2[(size_t)MTOT*DM];

// ---------------- helpers ------------------------------------------------------
__device__ __forceinline__ void mma_f16(float* d, const uint32_t* a, const uint32_t* b) {
    asm volatile(
        "mma.sync.aligned.m16n8k16.row.col.f32.f16.f16.f32 "
        "{%0,%1,%2,%3}, {%4,%5,%6,%7}, {%8,%9}, {%0,%1,%2,%3};"
        : "+f"(d[0]), "+f"(d[1]), "+f"(d[2]), "+f"(d[3])
        : "r"(a[0]), "r"(a[1]), "r"(a[2]), "r"(a[3]), "r"(b[0]), "r"(b[1]));
}
__device__ __forceinline__ void ldm_x4(uint32_t& r0, uint32_t& r1, uint32_t& r2, uint32_t& r3,
                                       uint32_t addr) {
    asm volatile("ldmatrix.sync.aligned.m8n8.x4.shared.b16 {%0,%1,%2,%3}, [%4];"
                 : "=r"(r0), "=r"(r1), "=r"(r2), "=r"(r3) : "r"(addr));
}
__device__ __forceinline__ void ldm_x4t(uint32_t& r0, uint32_t& r1, uint32_t& r2, uint32_t& r3,
                                        uint32_t addr) {
    asm volatile("ldmatrix.sync.aligned.m8n8.x4.trans.shared.b16 {%0,%1,%2,%3}, [%4];"
                 : "=r"(r0), "=r"(r1), "=r"(r2), "=r"(r3) : "r"(addr));
}
__device__ __forceinline__ uint32_t h2u(float x, float y) {
    __half2 h = __float22half2_rn(make_float2(x, y));
    return *(uint32_t*)&h;
}
__device__ __forceinline__ void cp16(uint32_t dst, const void* src) {
    asm volatile("cp.async.cg.shared.global [%0], [%1], 16;" :: "r"(dst), "l"(src));
}
#define CP_COMMIT() asm volatile("cp.async.commit_group;" ::: "memory")
#define CP_WAIT(N)  asm volatile("cp.async.wait_group %0;" :: "n"(N) : "memory")

// ---------------- one-shot conversion / concat kernel -------------------------
// Wq and bq are scaled by 1/sqrt(HD)=0.125 here, so Q leaves the QKV GEMM
// pre-scaled and flash_mma needs no per-tile scaling.
#define SRC_E (4194304u)
#define WE    (1048576u)

__device__ __forceinline__ void cvt8s(const float* in, __half* out, float s) {
    float4 a = *(const float4*)in;
    float4 b = *(const float4*)(in + 4);
    uint4 o;
    o.x = h2u(a.x * s, a.y * s); o.y = h2u(a.z * s, a.w * s);
    o.z = h2u(b.x * s, b.y * s); o.w = h2u(b.z * s, b.w * s);
    *(uint4*)out = o;
}
__device__ __forceinline__ void cvt8(const float* in, __half* out) {
    cvt8s(in, out, 1.0f);
}

__global__ __launch_bounds__(256)
void conv_all(const float* __restrict__ src,
              const float* __restrict__ Wq, const float* __restrict__ Wk,
              const float* __restrict__ Wv, const float* __restrict__ Wo,
              const float* __restrict__ W1, const float* __restrict__ W2,
              const float* __restrict__ bq, const float* __restrict__ bk,
              const float* __restrict__ bv,
              __half* __restrict__ srch, __half* __restrict__ Wqkv,
              __half* __restrict__ Woh, __half* __restrict__ W1h,
              __half* __restrict__ W2h, float* __restrict__ bqkv)
{
    const unsigned g = blockIdx.x * 256 + threadIdx.x;
    if (g < 384) {
        int t = g >> 7;
        int i = (g & 127) * 8;
        const float* bp = (t == 0) ? bq : (t == 1) ? bk : bv;
        const float sc = (t == 0) ? 0.125f : 1.0f;
        float4 a = *(const float4*)(bp + i);
        float4 b = *(const float4*)(bp + i + 4);
        a.x *= sc; a.y *= sc; a.z *= sc; a.w *= sc;
        b.x *= sc; b.y *= sc; b.z *= sc; b.w *= sc;
        *(float4*)(bqkv + t * 1024 + i)     = a;
        *(float4*)(bqkv + t * 1024 + i + 4) = b;
    }
    size_t i = (size_t)g * 8;
    if (i < SRC_E) {
        cvt8(src + i, srch + i);
    } else if (i < SRC_E + 3 * (size_t)WE) {
        size_t j = i - SRC_E;
        int t = (int)(j >> 20);
        size_t jj = j & (WE - 1);
        const float* W = (t == 0) ? Wq : (t == 1) ? Wk : Wv;
        const float sc = (t == 0) ? 0.125f : 1.0f;
        size_t k = jj >> 10, n = jj & 1023;
        cvt8s(W + jj, Wqkv + k * 3072 + t * 1024 + n, sc);
    } else if (i < SRC_E + 4 * (size_t)WE) {
        size_t j = i - (SRC_E + 3 * (size_t)WE);
        cvt8(Wo + j, Woh + j);
    } else if (i < SRC_E + 4 * (size_t)WE + SRC_E) {
        size_t j = i - (SRC_E + 4 * (size_t)WE);
        cvt8(W1 + j, W1h + j);
    } else {
        size_t j = i - (SRC_E + 4 * (size_t)WE + SRC_E);
        cvt8(W2 + j, W2h + j);
    }
}

// ---------------- warp-mma FP16 GEMM, KC=32, 4-stage, depth-3 (R9 optimum) ---
// EPI 0: fp32 plain  1: gelu fp16  2: split-head qkv-concat fp16 (N=3072)
#define KC 32
#define AS_STRIDE 40
#define BS_STRIDE 136
#define ASB (128 * AS_STRIDE * 2)      // 10240 B
#define BSB (KC * BS_STRIDE * 2)       // 8704 B
#define NSTAGE 4
#define GEMM_SMEM (NSTAGE * (ASB + BSB))   // 75776 B

template<int EPI>
__global__ __launch_bounds__(256)
void wm_gemm(const __half* __restrict__ A, const __half* __restrict__ B,
             const float* __restrict__ bias, void* __restrict__ Cv,
             int M, int N, int K)
{
    extern __shared__ __align__(16) char smem[];
    const uint32_t As_base = (uint32_t)__cvta_generic_to_shared(smem);
    const uint32_t Bs_base = As_base + NSTAGE * ASB;

    const int tid  = threadIdx.x;
    const int wid  = tid >> 5;
    const int lane = tid & 31;
    const int lg   = lane & 3;
    const int grp  = lane >> 2;
    const int n0 = blockIdx.x * 128;
    const int m0 = blockIdx.y * 128;
    const int wm = (wid & 3) * 32;
    const int wn = (wid >> 2) * 64;

    // staging (KC=32): A 128x32 halves, B 32x128 halves; 2 cp16 each per thread
    const int arow = tid >> 1, acol = (tid & 1) * 16;
    const int brow = tid >> 3, bcol = (tid & 7) * 16;
    const __half* Ap = A + (size_t)(m0 + arow) * K + acol;
    const __half* Bp = B + (size_t)brow * N + n0 + bcol;
    const uint32_t a_dst = As_base + arow * (AS_STRIDE * 2) + acol * 2;
    const uint32_t b_dst = Bs_base + brow * (BS_STRIDE * 2) + bcol * 2;

    const uint32_t a_addr0 = As_base +
        ((wm + (lane & 15)) * AS_STRIDE + (lane >> 4) * 8) * 2;
    const uint32_t b_addr0 = Bs_base +
        ((lane & 15) * BS_STRIDE + wn + (lane >> 4) * 8) * 2;

    float d[2][8][4];
    #pragma unroll
    for (int i = 0; i < 2; i++)
        #pragma unroll
        for (int j = 0; j < 8; j++)
            #pragma unroll
            for (int q = 0; q < 4; q++) d[i][j][q] = 0.f;

    const int C_CHUNKS = K >> 5;

    // prefetch chunks 0,1,2
    #pragma unroll
    for (int pc = 0; pc < 3; pc++) {
        cp16(a_dst + pc * ASB,      Ap + pc * KC);
        cp16(a_dst + pc * ASB + 16, Ap + pc * KC + 8);
        cp16(b_dst + pc * BSB,      Bp + (size_t)pc * KC * N);
        cp16(b_dst + pc * BSB + 16, Bp + (size_t)pc * KC * N + 8);
        CP_COMMIT();
    }

    for (int c = 0; c < C_CHUNKS; c++) {
        const int rb = c & 3;
        CP_WAIT(2);
        __syncthreads();
        if (c + 3 < C_CHUNKS) {
            const int wb = (c + 3) & 3;
            cp16(a_dst + wb * ASB,      Ap + (size_t)(c + 3) * KC);
            cp16(a_dst + wb * ASB + 16, Ap + (size_t)(c + 3) * KC + 8);
            cp16(b_dst + wb * BSB,      Bp + (size_t)(c + 3) * KC * N);
            cp16(b_dst + wb * BSB + 16, Bp + (size_t)(c + 3) * KC * N + 8);
        }
        CP_COMMIT();

        #pragma unroll
        for (int ks = 0; ks < 2; ks++) {
            uint32_t a[2][4], b[8][2];
            #pragma unroll
            for (int i = 0; i < 2; i++)
                ldm_x4(a[i][0], a[i][1], a[i][2], a[i][3],
                       a_addr0 + rb * ASB + (i * 16 * AS_STRIDE + ks * 16) * 2);
            #pragma unroll
            for (int j2 = 0; j2 < 4; j2++) {
                uint32_t r0, r1, r2, r3;
                ldm_x4t(r0, r1, r2, r3,
                        b_addr0 + rb * BSB + (ks * 16 * BS_STRIDE + j2 * 16) * 2);
                b[j2 * 2][0] = r0; b[j2 * 2][1] = r1;
                b[j2 * 2 + 1][0] = r2; b[j2 * 2 + 1][1] = r3;
            }
            #pragma unroll
            for (int i = 0; i < 2; i++)
                #pragma unroll
                for (int j = 0; j < 8; j++)
                    mma_f16(d[i][j], a[i], b[j]);
        }
    }

    // ---- epilogue ----
    #pragma unroll
    for (int i = 0; i < 2; i++) {
        const int r0 = m0 + wm + i * 16 + grp;
        #pragma unroll
        for (int j = 0; j < 8; j++) {
            const int c = n0 + wn + j * 8 + lg * 2;
            float2 v0, v1;
            v0.x = d[i][j][0] + bias[c];
            v0.y = d[i][j][1] + bias[c + 1];
            v1.x = d[i][j][2] + bias[c];
            v1.y = d[i][j][3] + bias[c + 1];
            if (EPI == 0) {
                float* C = (float*)Cv;
                *(float2*)(C + (size_t)r0 * N + c) = v0;
                *(float2*)(C + (size_t)(r0 + 8) * N + c) = v1;
            } else if (EPI == 1) {
                v0.x *= normcdff(v0.x); v0.y *= normcdff(v0.y);
                v1.x *= normcdff(v1.x); v1.y *= normcdff(v1.y);
                __half* C = (__half*)Cv;
                *(uint32_t*)(C + (size_t)r0 * N + c) = h2u(v0.x, v0.y);
                *(uint32_t*)(C + (size_t)(r0 + 8) * N + c) = h2u(v1.x, v1.y);
            } else {
                const int t_ = c >> 10, n = c & 1023;
                const int h = n >> 6, hd = n & 63;
                const int b0_ = r0 >> 11, l0 = r0 & 2047;
                const int r1 = r0 + 8;
                const int b1_ = r1 >> 11, l1 = r1 & 2047;
                __half* C = (__half*)Cv + (size_t)t_ * HSZ;
                *(uint32_t*)(C + ((size_t)((b0_ << 4) + h) * LL + l0) * HD + hd) = h2u(v0.x, v0.y);
                *(uint32_t*)(C + ((size_t)((b1_ << 4) + h) * LL + l1) * HD + hd) = h2u(v1.x, v1.y);
            }
        }
    }
}

// ---------------- flash attention: 128-query blocks, 8 warps -----------------
// Q arrives pre-scaled by 1/sqrt(HD) (folded into Wq/bq at conversion).
#define FS 72
#define KVB (64 * FS * 2)

__global__ __launch_bounds__(256)
void flash_mma(const __half* __restrict__ Q, const __half* __restrict__ Kg,
               const __half* __restrict__ Vg, __half* __restrict__ O)
{
    __shared__ __align__(16) uint16_t Qs[128][FS];
    __shared__ __align__(16) uint16_t Ks[2][64][FS];
    __shared__ __align__(16) uint16_t Vs[2][64][FS];

    const int tid  = threadIdx.x;
    const int wid  = tid >> 5;
    const int lane = tid & 31;
    const int grp  = lane >> 2;
    const int lg   = lane & 3;
    const int bh   = blockIdx.y;
    const int q0   = blockIdx.x * 128;

    const uint32_t Qb_s = (uint32_t)__cvta_generic_to_shared(&Qs[0][0]);
    const uint32_t Kb_s = (uint32_t)__cvta_generic_to_shared(&Ks[0][0][0]);
    const uint32_t Vb_s = (uint32_t)__cvta_generic_to_shared(&Vs[0][0][0]);

    const int qrow = tid >> 1, qcol = (tid & 1) * 32;
    const uint32_t q_dst = Qb_s + qrow * (FS * 2) + qcol * 2;
    const __half* Qp = Q + ((size_t)bh * LL + q0 + qrow) * HD + qcol;
    const int krow = tid >> 2, kcol = (tid & 3) * 16;
    const uint32_t k_dst = Kb_s + krow * (FS * 2) + kcol * 2;
    const uint32_t v_dst = Vb_s + krow * (FS * 2) + kcol * 2;
    const __half* Kp = Kg + ((size_t)bh * LL + krow) * HD + kcol;
    const __half* Vp = Vg + ((size_t)bh * LL + krow) * HD + kcol;

    #pragma unroll
    for (int i = 0; i < 4; i++) cp16(q_dst + i * 16, Qp + i * 8);
    CP_COMMIT();
    #pragma unroll
    for (int pt = 0; pt < 2; pt++) {
        #pragma unroll
        for (int i = 0; i < 2; i++) {
            cp16(k_dst + pt * KVB + i * 16, Kp + (size_t)pt * 64 * HD + i * 8);
            cp16(v_dst + pt * KVB + i * 16, Vp + (size_t)pt * 64 * HD + i * 8);
        }
        CP_COMMIT();
    }

    CP_WAIT(2);
    __syncthreads();
    uint32_t qa[4][4];
    {
        const uint32_t qaddr = Qb_s + ((wid * 16 + (lane & 15)) * FS + (lane >> 4) * 8) * 2;
        #pragma unroll
        for (int ks = 0; ks < 4; ks++)
            ldm_x4(qa[ks][0], qa[ks][1], qa[ks][2], qa[ks][3], qaddr + ks * 16 * 2);
    }

    const uint32_t kaddr = Kb_s +
        (((lane >> 4) * 8 + (lane & 7)) * FS + ((lane >> 3) & 1) * 8) * 2;
    const uint32_t vaddr = Vb_s + ((lane & 15) * FS + (lane >> 4) * 8) * 2;

    float m0 = -1e30f, m1 = -1e30f, l0 = 0.f, l1 = 0.f;
    float oacc[8][4];
    #pragma unroll
    for (int j = 0; j < 8; j++)
        #pragma unroll
        for (int q = 0; q < 4; q++) oacc[j][q] = 0.f;

    const int NT = LL / 64;
    for (int kt = 0; kt < NT; kt++) {
        const int buf = kt & 1;
        CP_WAIT(1);
        __syncthreads();

        float sacc[8][4];
        #pragma unroll
        for (int na = 0; na < 8; na++)
            #pragma unroll
            for (int q = 0; q < 4; q++) sacc[na][q] = 0.f;

        #pragma unroll
        for (int ks = 0; ks < 4; ks++) {
            #pragma unroll
            for (int na2 = 0; na2 < 4; na2++) {
                uint32_t b0, b1, b2, b3;
                ldm_x4(b0, b1, b2, b3,
                       kaddr + buf * KVB + (na2 * 16 * FS + ks * 16) * 2);
                uint32_t bb0[2] = {b0, b1};
                uint32_t bb1[2] = {b2, b3};
                mma_f16(sacc[na2 * 2], qa[ks], bb0);
                mma_f16(sacc[na2 * 2 + 1], qa[ks], bb1);
            }
        }

        float tm0 = -1e30f, tm1 = -1e30f;
        #pragma unroll
        for (int na = 0; na < 8; na++) {
            tm0 = fmaxf(tm0, fmaxf(sacc[na][0], sacc[na][1]));
            tm1 = fmaxf(tm1, fmaxf(sacc[na][2], sacc[na][3]));
        }
        tm0 = fmaxf(tm0, __shfl_xor_sync(0xffffffffu, tm0, 1));
        tm0 = fmaxf(tm0, __shfl_xor_sync(0xffffffffu, tm0, 2));
        tm1 = fmaxf(tm1, __shfl_xor_sync(0xffffffffu, tm1, 1));
        tm1 = fmaxf(tm1, __shfl_xor_sync(0xffffffffu, tm1, 2));
        const float nm0 = fmaxf(m0, tm0), nm1 = fmaxf(m1, tm1);
        const float f0 = __expf(m0 - nm0), f1 = __expf(m1 - nm1);
        m0 = nm0; m1 = nm1;

        float s0 = 0.f, s1 = 0.f;
        uint32_t pa[4][4];
        #pragma unroll
        for (int na = 0; na < 8; na++) {
            float p0 = __expf(sacc[na][0] - nm0);
            float p1 = __expf(sacc[na][1] - nm0);
            float p2 = __expf(sacc[na][2] - nm1);
            float p3 = __expf(sacc[na][3] - nm1);
            s0 += p0 + p1; s1 += p2 + p3;
            pa[na >> 1][(na & 1) * 2 + 0] = h2u(p0, p1);
            pa[na >> 1][(na & 1) * 2 + 1] = h2u(p2, p3);
        }
        s0 += __shfl_xor_sync(0xffffffffu, s0, 1);
        s0 += __shfl_xor_sync(0xffffffffu, s0, 2);
        s1 += __shfl_xor_sync(0xffffffffu, s1, 1);
        s1 += __shfl_xor_sync(0xffffffffu, s1, 2);
        l0 = l0 * f0 + s0;
        l1 = l1 * f1 + s1;
        #pragma unroll
        for (int j = 0; j < 8; j++) {
            oacc[j][0] *= f0; oacc[j][1] *= f0;
            oacc[j][2] *= f1; oacc[j][3] *= f1;
        }

        #pragma unroll
        for (int ks = 0; ks < 4; ks++) {
            #pragma unroll
            for (int j2 = 0; j2 < 4; j2++) {
                uint32_t r0, r1, r2, r3;
                ldm_x4t(r0, r1, r2, r3,
                        vaddr + buf * KVB + (ks * 16 * FS + j2 * 16) * 2);
                uint32_t bb0[2] = {r0, r1};
                uint32_t bb1[2] = {r2, r3};
                mma_f16(oacc[j2 * 2], pa[ks], bb0);
                mma_f16(oacc[j2 * 2 + 1], pa[ks], bb1);
            }
        }
        __syncthreads();
        if (kt + 2 < NT) {
            #pragma unroll
            for (int i = 0; i < 2; i++) {
                cp16(k_dst + buf * KVB + i * 16, Kp + (size_t)(kt + 2) * 64 * HD + i * 8);
                cp16(v_dst + buf * KVB + i * 16, Vp + (size_t)(kt + 2) * 64 * HD + i * 8);
            }
        }
        CP_COMMIT();
    }

    const float inv0 = 1.f / l0, inv1 = 1.f / l1;
    const int b = bh >> 4, h = bh & 15;
    const int r0 = q0 + wid * 16 + grp;
    __half* O0 = O + ((size_t)(b * LL + r0)) * DM + h * HD;
    __half* O1 = O0 + (size_t)8 * DM;
    #pragma unroll
    for (int j = 0; j < 8; j++) {
        *(uint32_t*)(O0 + j * 8 + 2 * lg) = h2u(oacc[j][0] * inv0, oacc[j][1] * inv0);
        *(uint32_t*)(O1 + j * 8 + 2 * lg) = h2u(oacc[j][2] * inv1, oacc[j][3] * inv1);
    }
}

// ---------------- warp-per-row residual add + LayerNorm (barrier-free) ------
template<bool WRITE_H>
__global__ __launch_bounds__(256)
void add_ln_k(const float* __restrict__ A, const float* __restrict__ B,
              const float* __restrict__ gamma, const float* __restrict__ beta,
              float* __restrict__ out, __half* __restrict__ outh)
{
    const int w = threadIdx.x >> 5, lane = threadIdx.x & 31;
    const int row = blockIdx.x * 8 + w;
    const float4* a = (const float4*)(A + (size_t)row * DM);
    const float4* b = (const float4*)(B + (size_t)row * DM);

    float4 v[8];
    float s = 0.f, q = 0.f;
    #pragma unroll
    for (int i = 0; i < 8; i++) {
        float4 va = a[lane + 32 * i];
        float4 vb = b[lane + 32 * i];
        va.x += vb.x; va.y += vb.y; va.z += vb.z; va.w += vb.w;
        v[i] = va;
        s += va.x + va.y + va.z + va.w;
        q += va.x * va.x + va.y * va.y + va.z * va.z + va.w * va.w;
    }
    #pragma unroll
    for (int o = 16; o > 0; o >>= 1) {
        s += __shfl_xor_sync(0xffffffffu, s, o);
        q += __shfl_xor_sync(0xffffffffu, q, o);
    }
    const float mean = s * (1.f / DM);
    const float var  = q * (1.f / DM) - mean * mean;
    const float rstd = rsqrtf(var + 1e-5f);

    #pragma unroll
    for (int i = 0; i < 8; i++) {
        const int c = (lane + 32 * i) * 4;
        float4 g  = *(const float4*)(gamma + c);
        float4 be = *(const float4*)(beta + c);
        float4 o;
        o.x = (v[i].x - mean) * rstd * g.x + be.x;
        o.y = (v[i].y - mean) * rstd * g.y + be.y;
        o.z = (v[i].z - mean) * rstd * g.z + be.z;
        o.w = (v[i].w - mean) * rstd * g.w + be.w;
        ((float4*)(out + (size_t)row * DM))[lane + 32 * i] = o;
        if (WRITE_H) {
            uint2 hh = make_uint2(h2u(o.x, o.y), h2u(o.z, o.w));
            *(uint2*)(outh + (size_t)row * DM + c) = hh;
        }
    }
}

// ---------------- launcher ---------------------------------------------------
extern "C" void kernel_launch(void* const* d_in, const int* in_sizes, int n_in,
                              void* d_out, int out_size)
{
    const float* src = (const float*)d_in[0];
    const float* Wq  = (const float*)d_in[1];  const float* bq = (const float*)d_in[2];
    const float* Wk  = (const float*)d_in[3];  const float* bk = (const float*)d_in[4];
    const float* Wv  = (const float*)d_in[5];  const float* bv = (const float*)d_in[6];
    const float* Wo  = (const float*)d_in[7];  const float* bo = (const float*)d_in[8];
    const float* W1  = (const float*)d_in[9];  const float* b1 = (const float*)d_in[10];
    const float* W2  = (const float*)d_in[11]; const float* b2 = (const float*)d_in[12];
    const float* gamma1 = (const float*)d_in[13]; const float* beta1 = (const float*)d_in[14];
    const float* gamma2 = (const float*)d_in[15]; const float* beta2 = (const float*)d_in[16];
    float* out = (float*)d_out;

    __half *srch, *Wqkvh, *Woh, *W1h, *W2h, *QKVh, *attnh, *xh, *ff1h;
    float  *bqkv, *proj, *x, *ff2;
    cudaGetSymbolAddress((void**)&srch,  g_srch);
    cudaGetSymbolAddress((void**)&Wqkvh, g_Wqkvh);
    cudaGetSymbolAddress((void**)&bqkv,  g_bqkv);
    cudaGetSymbolAddress((void**)&Woh,   g_Woh);
    cudaGetSymbolAddress((void**)&W1h,   g_W1h);
    cudaGetSymbolAddress((void**)&W2h,   g_W2h);
    cudaGetSymbolAddress((void**)&QKVh,  g_QKVh);
    cudaGetSymbolAddress((void**)&attnh, g_attnh);
    cudaGetSymbolAddress((void**)&xh,    g_xh);
    cudaGetSymbolAddress((void**)&ff1h,  g_ff1h);
    cudaGetSymbolAddress((void**)&proj,  g_proj);
    cudaGetSymbolAddress((void**)&x,     g_x);
    cudaGetSymbolAddress((void**)&ff2,   g_ff2);

    cudaFuncSetAttribute(wm_gemm<0>, cudaFuncAttributeMaxDynamicSharedMemorySize, GEMM_SMEM);
    cudaFuncSetAttribute(wm_gemm<1>, cudaFuncAttributeMaxDynamicSharedMemorySize, GEMM_SMEM);
    cudaFuncSetAttribute(wm_gemm<2>, cudaFuncAttributeMaxDynamicSharedMemorySize, GEMM_SMEM);

    conv_all<<<8192, 256>>>(src, Wq, Wk, Wv, Wo, W1, W2, bq, bk, bv,
                            srch, Wqkvh, Woh, W1h, W2h, bqkv);

    wm_gemm<2><<<dim3(3 * DM / 128, MTOT / 128), 256, GEMM_SMEM>>>(
        srch, Wqkvh, bqkv, QKVh, MTOT, 3 * DM, DM);

    flash_mma<<<dim3(LL / 128, BB * NH), 256>>>(QKVh, QKVh + HSZ, QKVh + 2 * HSZ, attnh);

    wm_gemm<0><<<dim3(DM / 128, MTOT / 128), 256, GEMM_SMEM>>>(attnh, Woh, bo, proj, MTOT, DM, DM);

    add_ln_k<true><<<MTOT / 8, 256>>>(src, proj, gamma1, beta1, x, xh);

    wm_gemm<1><<<dim3(DFF / 128, MTOT / 128), 256, GEMM_SMEM>>>(xh, W1h, b1, ff1h, MTOT, DFF, DM);
    wm_gemm<0><<<dim3(DM / 128, MTOT / 128), 256, GEMM_SMEM>>>(ff1h, W2h, b2, ff2, MTOT, DM, DFF);

    add_ln_k<false><<<MTOT / 8, 256>>>(x, ff2, gamma2, beta2, out, nullptr);
}